// round 1
// baseline (speedup 1.0000x reference)
#include <cuda_runtime.h>
#include <cuda_bf16.h>
#include <cstddef>

// ---------------- problem constants ----------------
#define D_MODEL 1024
#define N_LAYER 4
#define VOCAB   32000
#define D_STATE 16
#define D_INNER 2048
#define D_CONV  4
#define BATCH   2
#define SEQ     1024
#define M_ROWS  (BATCH * SEQ)     // 2048

// ---------------- scratch (device globals; no allocation allowed) ----------
__device__ float g_X [M_ROWS * D_MODEL];   // residual stream
__device__ float g_XN[M_ROWS * D_MODEL];   // rmsnorm output
__device__ float g_H [M_ROWS * D_INNER];   // in-proj output
__device__ float g_RES[M_ROWS * D_INNER];  // silu(res-proj)
__device__ float g_U [M_ROWS * D_INNER];   // silu(conv)
__device__ float g_YR[M_ROWS * D_INNER];   // (scan y) * res
__device__ float g_B [M_ROWS * D_STATE];
__device__ float g_C [M_ROWS * D_STATE];
__device__ float g_dt[M_ROWS];

// ---------------- small helpers ----------------
__device__ __forceinline__ float silu_f(float x) {
    return x / (1.f + __expf(-x));
}
__device__ __forceinline__ float softplus_f(float x) {
    return x > 20.f ? x : log1pf(__expf(x));
}

// ---------------- embedding gather ----------------
__global__ void embed_kernel(const float* __restrict__ emb,
                             const int* __restrict__ ids,
                             float* __restrict__ X) {
    int t = blockIdx.x * blockDim.x + threadIdx.x;      // over M_ROWS*D_MODEL
    int row = t >> 10;            // /1024
    int col = t & 1023;
    X[t] = emb[(size_t)ids[row] * D_MODEL + col];
}

// ---------------- rmsnorm (one block per row of 1024) ----------------
__global__ void rmsnorm_kernel(const float* __restrict__ X,
                               const float* __restrict__ w,
                               float* __restrict__ out) {
    int row = blockIdx.x;
    const float* x = X + (size_t)row * D_MODEL;
    float s = 0.f;
    for (int i = threadIdx.x; i < D_MODEL; i += 256) {
        float v = x[i];
        s += v * v;
    }
    __shared__ float red[256];
    red[threadIdx.x] = s;
    __syncthreads();
    for (int o = 128; o; o >>= 1) {
        if (threadIdx.x < o) red[threadIdx.x] += red[threadIdx.x + o];
        __syncthreads();
    }
    float scale = rsqrtf(red[0] * (1.f / D_MODEL) + 1e-5f);
    for (int i = threadIdx.x; i < D_MODEL; i += 256)
        out[(size_t)row * D_MODEL + i] = x[i] * scale * w[i];
}

// ---------------- depthwise causal conv + silu ----------------
__global__ void conv_kernel(const float* __restrict__ H,
                            const float* __restrict__ cw,   // (D_INNER,4)
                            const float* __restrict__ cb,
                            float* __restrict__ Uo) {
    int t = blockIdx.x * blockDim.x + threadIdx.x;     // over M_ROWS*D_INNER
    int d  = t & (D_INNER - 1);
    int bl = t >> 11;                                   // /2048
    int l  = bl & (SEQ - 1);
    float acc = cb[d];
#pragma unroll
    for (int j = 0; j < D_CONV; j++) {
        int ll = l - (D_CONV - 1) + j;
        if (ll >= 0)
            acc += H[(size_t)(bl - l + ll) * D_INNER + d] * cw[d * D_CONV + j];
    }
    Uo[t] = silu_f(acc);
}

// ---------------- B, C, dt projections (one block per token row) --------
__global__ void bc_kernel(const float* __restrict__ U,
                          const float* __restrict__ wB, const float* __restrict__ bB,
                          const float* __restrict__ wC, const float* __restrict__ bC,
                          const float* __restrict__ wdt, const float* __restrict__ bdt,
                          float* __restrict__ Bm, float* __restrict__ Cm,
                          float* __restrict__ dtb) {
    int bl = blockIdx.x;                       // 0..M_ROWS-1
    __shared__ float su[D_INNER];
    const float* u = U + (size_t)bl * D_INNER;
    for (int i = threadIdx.x; i < D_INNER; i += 256) su[i] = u[i];
    __syncthreads();
    int warp = threadIdx.x >> 5, lane = threadIdx.x & 31;
    for (int j = warp; j < 2 * D_STATE + 1; j += 8) {
        const float* w = (j < D_STATE) ? wB + (size_t)j * D_INNER
                       : (j < 2 * D_STATE) ? wC + (size_t)(j - D_STATE) * D_INNER
                       : wdt;
        float s = 0.f;
        for (int i = lane; i < D_INNER; i += 32) s += su[i] * w[i];
#pragma unroll
        for (int o = 16; o; o >>= 1) s += __shfl_down_sync(0xffffffffu, s, o);
        if (lane == 0) {
            if (j < D_STATE)           Bm[bl * D_STATE + j] = s + bB[j];
            else if (j < 2 * D_STATE)  Cm[bl * D_STATE + (j - D_STATE)] = s + bC[j - D_STATE];
            else                       dtb[bl] = s + bdt[0];
        }
    }
}

// ---------------- selective scan (thread per (b,d), sequential in L) ----
__global__ void scan_kernel(const float* __restrict__ U,
                            const float* __restrict__ RES,
                            const float* __restrict__ Bm,
                            const float* __restrict__ Cm,
                            const float* __restrict__ dtb,
                            const float* __restrict__ A_log,
                            const float* __restrict__ tau,
                            const float* __restrict__ Dp,
                            float* __restrict__ YR) {
    int d = blockIdx.x * blockDim.x + threadIdx.x;   // 0..D_INNER-1
    int b = blockIdx.y;
    float a[D_STATE], h[D_STATE];
#pragma unroll
    for (int n = 0; n < D_STATE; n++) {
        a[n] = -__expf(A_log[(size_t)d * D_STATE + n]);
        h[n] = 0.f;
    }
    float tau_d = tau[d], dpv = Dp[d];
    const float* Up = U   + (size_t)b * SEQ * D_INNER + d;
    const float* Rp = RES + (size_t)b * SEQ * D_INNER + d;
    float*       Yp = YR  + (size_t)b * SEQ * D_INNER + d;
    const float* Bp = Bm  + (size_t)b * SEQ * D_STATE;
    const float* Cp = Cm  + (size_t)b * SEQ * D_STATE;
    const float* Tp = dtb + (size_t)b * SEQ;

    for (int l = 0; l < SEQ; l++) {
        float delta = softplus_f(tau_d + Tp[l]);
        float u  = Up[(size_t)l * D_INNER];
        float du = delta * u;
        float y  = 0.f;
#pragma unroll
        for (int n = 0; n < D_STATE; n++) {
            float dA = __expf(delta * a[n]);
            h[n] = dA * h[n] + du * Bp[l * D_STATE + n];
            y += Cp[l * D_STATE + n] * h[n];
        }
        Yp[(size_t)l * D_INNER] = (y + dpv * u) * Rp[(size_t)l * D_INNER];
    }
}

// ---------------- GEMM: C[m,n] = sum_k A[m,k] * W[n,k] (+bias, epilogue) --
// A: (M,K) row-major, W: (N,K) row-major. BM=128, BN=64, BK=16, 256 thr.
// EPI: 0 = store, 1 = silu then store, 2 = accumulate into C (residual)
#define GBM 128
#define GBN 64
#define GBK 16

template <int EPI>
__global__ void gemm_nt(const float* __restrict__ A,
                        const float* __restrict__ W,
                        const float* __restrict__ bias,
                        float* __restrict__ C,
                        int M, int N, int K) {
    __shared__ float As[GBK][GBM];
    __shared__ float Bs[GBK][GBN];
    int m0 = blockIdx.y * GBM, n0 = blockIdx.x * GBN;
    int tid = threadIdx.x;
    int tm = tid >> 4, tn = tid & 15;   // tm 0..15 (8 rows each), tn 0..15 (4 cols each)

    float acc[8][4];
#pragma unroll
    for (int i = 0; i < 8; i++)
#pragma unroll
        for (int j = 0; j < 4; j++) acc[i][j] = 0.f;

    for (int k0 = 0; k0 < K; k0 += GBK) {
        // load A tile (128x16) as float4, store transposed
#pragma unroll
        for (int it = 0; it < 2; it++) {
            int idx4 = tid + it * 256;          // 0..511
            int row = idx4 >> 2, c4 = idx4 & 3;
            float4 v = *(const float4*)(A + (size_t)(m0 + row) * K + k0 + c4 * 4);
            As[c4 * 4 + 0][row] = v.x;
            As[c4 * 4 + 1][row] = v.y;
            As[c4 * 4 + 2][row] = v.z;
            As[c4 * 4 + 3][row] = v.w;
        }
        // load W tile (64x16)
        {
            int row = tid >> 2, c4 = tid & 3;
            float4 v = *(const float4*)(W + (size_t)(n0 + row) * K + k0 + c4 * 4);
            Bs[c4 * 4 + 0][row] = v.x;
            Bs[c4 * 4 + 1][row] = v.y;
            Bs[c4 * 4 + 2][row] = v.z;
            Bs[c4 * 4 + 3][row] = v.w;
        }
        __syncthreads();
#pragma unroll
        for (int k = 0; k < GBK; k++) {
            float4 a0 = *(const float4*)&As[k][tm * 8];
            float4 a1 = *(const float4*)&As[k][tm * 8 + 4];
            float4 bb = *(const float4*)&Bs[k][tn * 4];
            float av[8] = {a0.x, a0.y, a0.z, a0.w, a1.x, a1.y, a1.z, a1.w};
            float bv[4] = {bb.x, bb.y, bb.z, bb.w};
#pragma unroll
            for (int i = 0; i < 8; i++)
#pragma unroll
                for (int j = 0; j < 4; j++) acc[i][j] += av[i] * bv[j];
        }
        __syncthreads();
    }
    // epilogue
#pragma unroll
    for (int j = 0; j < 4; j++) {
        int n = n0 + tn * 4 + j;
        float bvv = bias ? bias[n] : 0.f;
#pragma unroll
        for (int i = 0; i < 8; i++) {
            int m = m0 + tm * 8 + i;
            float v = acc[i][j] + bvv;
            if (EPI == 1) v = silu_f(v);
            size_t off = (size_t)m * N + n;
            if (EPI == 2) C[off] += v;
            else          C[off] = v;
        }
    }
}

// ---------------- launch ----------------
extern "C" void kernel_launch(void* const* d_in, const int* in_sizes, int n_in,
                              void* d_out, int out_size) {
    const float* emb     = (const float*)d_in[0];
    const float* norm_w  = (const float*)d_in[1];
    const float* w_in    = (const float*)d_in[2];
    const float* b_in    = (const float*)d_in[3];
    const float* w_res   = (const float*)d_in[4];
    const float* b_res   = (const float*)d_in[5];
    const float* conv_w  = (const float*)d_in[6];
    const float* conv_b  = (const float*)d_in[7];
    const float* w_B     = (const float*)d_in[8];
    const float* b_B     = (const float*)d_in[9];
    const float* w_C     = (const float*)d_in[10];
    const float* b_C     = (const float*)d_in[11];
    const float* w_dt    = (const float*)d_in[12];
    const float* b_dt    = (const float*)d_in[13];
    const float* tau_dt  = (const float*)d_in[14];
    const float* A_log   = (const float*)d_in[15];
    const float* Dp      = (const float*)d_in[16];
    const float* w_out   = (const float*)d_in[17];
    const float* b_out   = (const float*)d_in[18];
    const float* fnw     = (const float*)d_in[19];
    const int*   ids     = (const int*)d_in[20];
    float* out = (float*)d_out;

    float *pX, *pXN, *pH, *pRES, *pU, *pYR, *pB, *pC, *pDT;
    cudaGetSymbolAddress((void**)&pX,  g_X);
    cudaGetSymbolAddress((void**)&pXN, g_XN);
    cudaGetSymbolAddress((void**)&pH,  g_H);
    cudaGetSymbolAddress((void**)&pRES,g_RES);
    cudaGetSymbolAddress((void**)&pU,  g_U);
    cudaGetSymbolAddress((void**)&pYR, g_YR);
    cudaGetSymbolAddress((void**)&pB,  g_B);
    cudaGetSymbolAddress((void**)&pC,  g_C);
    cudaGetSymbolAddress((void**)&pDT, g_dt);

    embed_kernel<<<(M_ROWS * D_MODEL) / 256, 256>>>(emb, ids, pX);

    for (int i = 0; i < N_LAYER; i++) {
        const float* wi  = w_in  + (size_t)i * D_INNER * D_MODEL;
        const float* bi  = b_in  + (size_t)i * D_INNER;
        const float* wr  = w_res + (size_t)i * D_INNER * D_INNER;
        const float* br  = b_res + (size_t)i * D_INNER;
        const float* cw  = conv_w + (size_t)i * D_INNER * D_CONV;
        const float* cb  = conv_b + (size_t)i * D_INNER;
        const float* wB  = w_B  + (size_t)i * D_STATE * D_INNER;
        const float* bB  = b_B  + (size_t)i * D_STATE;
        const float* wC  = w_C  + (size_t)i * D_STATE * D_INNER;
        const float* bC  = b_C  + (size_t)i * D_STATE;
        const float* wdt = w_dt + (size_t)i * D_INNER;
        const float* bdt = b_dt + (size_t)i;
        const float* tau = tau_dt + (size_t)i * D_INNER;
        const float* Al  = A_log + (size_t)i * D_INNER * D_STATE;
        const float* dp  = Dp    + (size_t)i * D_INNER;
        const float* wo  = w_out + (size_t)i * D_MODEL * D_INNER;
        const float* bo  = b_out + (size_t)i * D_MODEL;
        const float* nw  = norm_w + (size_t)i * D_MODEL;

        rmsnorm_kernel<<<M_ROWS, 256>>>(pX, nw, pXN);

        gemm_nt<0><<<dim3(D_INNER / GBN, M_ROWS / GBM), 256>>>(
            pXN, wi, bi, pH, M_ROWS, D_INNER, D_MODEL);

        gemm_nt<1><<<dim3(D_INNER / GBN, M_ROWS / GBM), 256>>>(
            pH, wr, br, pRES, M_ROWS, D_INNER, D_INNER);

        conv_kernel<<<(M_ROWS * D_INNER) / 256, 256>>>(pH, cw, cb, pU);

        bc_kernel<<<M_ROWS, 256>>>(pU, wB, bB, wC, bC, wdt, bdt, pB, pC, pDT);

        scan_kernel<<<dim3(D_INNER / 256, BATCH), 256>>>(
            pU, pRES, pB, pC, pDT, Al, tau, dp, pYR);

        gemm_nt<2><<<dim3(D_MODEL / GBN, M_ROWS / GBM), 256>>>(
            pYR, wo, bo, pX, M_ROWS, D_MODEL, D_INNER);
    }

    rmsnorm_kernel<<<M_ROWS, 256>>>(pX, fnw, pXN);

    gemm_nt<0><<<dim3(VOCAB / GBN, M_ROWS / GBM), 256>>>(
        pXN, emb, nullptr, out, M_ROWS, VOCAB, D_MODEL);
}